// round 1
// baseline (speedup 1.0000x reference)
#include <cuda_runtime.h>
#include <cstdint>

#define BATCH 16
#define NH 4
#define HEADS (BATCH*NH)      // 64
#define D 64
#define S 1024
#define NELEM (HEADS*D*S)     // 4194304 per tensor

// ---- scratch (device globals; no runtime allocation) ----
__device__ int8_t  g_q8[HEADS*S*D];            // [head][s][d]  4MB
__device__ int8_t  g_k8[HEADS*S*D];            // [head][t][d]  4MB
__device__ int8_t  g_v8[HEADS*D*S];            // [head][d][t]  4MB
__device__ float   g_P[(size_t)HEADS*S*S];     // [head][s][t]  256MB
__device__ unsigned g_stat[4];                  // absmax bits: q,k,v ; maxprob bits

// ------------------------------------------------------------------
__global__ void k_init() {
    g_stat[0] = 0u; g_stat[1] = 0u; g_stat[2] = 0u; g_stat[3] = 0u;
}

// ------------------------------------------------------------------
// blockIdx.y selects tensor (0=q,1=k,2=v). Values are nonnegative after fabs,
// so uint bit compare == float compare.
__global__ void k_absmax(const float* __restrict__ q,
                         const float* __restrict__ k,
                         const float* __restrict__ v) {
    const float* p = (blockIdx.y == 0) ? q : ((blockIdx.y == 1) ? k : v);
    const float4* p4 = (const float4*)p;
    const int n4 = NELEM / 4;
    float m = 0.0f;
    for (int i = blockIdx.x * blockDim.x + threadIdx.x; i < n4;
         i += gridDim.x * blockDim.x) {
        float4 x = p4[i];
        m = fmaxf(m, fmaxf(fmaxf(fabsf(x.x), fabsf(x.y)),
                           fmaxf(fabsf(x.z), fabsf(x.w))));
    }
    #pragma unroll
    for (int o = 16; o; o >>= 1) m = fmaxf(m, __shfl_xor_sync(0xffffffffu, m, o));
    __shared__ float sm[8];
    if ((threadIdx.x & 31) == 0) sm[threadIdx.x >> 5] = m;
    __syncthreads();
    if (threadIdx.x == 0) {
        float t = sm[0];
        #pragma unroll
        for (int w = 1; w < 8; w++) t = fmaxf(t, sm[w]);
        atomicMax(&g_stat[blockIdx.y], __float_as_uint(t));
    }
}

// ------------------------------------------------------------------
// Quantize + transpose q/k:  in [head][d][s] (float) -> out [head][s][d] (int8)
// grid (S/64, HEADS, 2), block 256
__global__ void k_quantT(const float* __restrict__ q, const float* __restrict__ k) {
    const float* src = (blockIdx.z == 0) ? q : k;
    int8_t* dst = (blockIdx.z == 0) ? g_q8 : g_k8;
    const float amax = __uint_as_float(g_stat[blockIdx.z]);
    const float scale = fmaxf(__fdiv_rn(amax, 127.0f), 1e-8f);
    const int head = blockIdx.y;
    const int s0 = blockIdx.x * 64;
    __shared__ int8_t tile[64][68];
    const int t = threadIdx.x;
    #pragma unroll
    for (int i = 0; i < 16; i++) {
        int dd = i * 4 + (t >> 6);
        int ss = t & 63;
        float val = src[((size_t)(head * D + dd)) * S + s0 + ss];
        float r = rintf(__fdiv_rn(val, scale));
        r = fminf(fmaxf(r, -127.0f), 127.0f);
        tile[dd][ss] = (int8_t)r;
    }
    __syncthreads();
    #pragma unroll
    for (int i = 0; i < 4; i++) {
        int ss = i * 16 + (t >> 4);
        int d4 = (t & 15) * 4;
        char4 c;
        c.x = tile[d4 + 0][ss]; c.y = tile[d4 + 1][ss];
        c.z = tile[d4 + 2][ss]; c.w = tile[d4 + 3][ss];
        *(char4*)&dst[((size_t)(head * S + s0 + ss)) * D + d4] = c;
    }
}

// ------------------------------------------------------------------
// Quantize v in-layout: [head][d][t] float -> int8. One warp per (head,d) row.
// grid 512, block 256
__global__ void k_quantV(const float* __restrict__ v) {
    const float amax = __uint_as_float(g_stat[2]);
    const float scale = fmaxf(__fdiv_rn(amax, 127.0f), 1e-8f);
    const int row = blockIdx.x * 8 + (threadIdx.x >> 5);   // 0..4095
    const int lane = threadIdx.x & 31;
    const float4* src = (const float4*)(v + (size_t)row * S);
    char4* dst = (char4*)(g_v8 + (size_t)row * S);
    #pragma unroll
    for (int i = 0; i < 8; i++) {
        int idx = lane + 32 * i;
        float4 x = src[idx];
        char4 c;
        c.x = (int8_t)fminf(fmaxf(rintf(__fdiv_rn(x.x, scale)), -127.0f), 127.0f);
        c.y = (int8_t)fminf(fmaxf(rintf(__fdiv_rn(x.y, scale)), -127.0f), 127.0f);
        c.z = (int8_t)fminf(fmaxf(rintf(__fdiv_rn(x.z, scale)), -127.0f), 127.0f);
        c.w = (int8_t)fminf(fmaxf(rintf(__fdiv_rn(x.w, scale)), -127.0f), 127.0f);
        dst[idx] = c;
    }
}

// ------------------------------------------------------------------
// Pass 1: logits (dp4a, exact int), softmax, store P, track max prob = rcp(denom)
// grid (S/32, HEADS), block (32,8)=256
__global__ __launch_bounds__(256, 1) void k_pass1() {
    const int head = blockIdx.y;
    const int s0 = blockIdx.x * 32;
    const int tx = threadIdx.x & 31;
    const int ty = threadIdx.x >> 5;

    __shared__ int Asm[32][17];
    __shared__ int Bsm[512][17];

    const int* qi = (const int*)g_q8;
    const int* ki = (const int*)g_k8;

    int acc[4][32];
    #pragma unroll
    for (int r = 0; r < 4; r++)
        #pragma unroll
        for (int j = 0; j < 32; j++) acc[r][j] = 0;

    // load A tile: 32 rows x 16 ints
    for (int idx = threadIdx.x; idx < 32 * 16; idx += 256)
        Asm[idx >> 4][idx & 15] =
            qi[((size_t)(head * S + s0 + (idx >> 4))) * 16 + (idx & 15)];

    #pragma unroll
    for (int tc = 0; tc < 2; tc++) {
        if (tc) __syncthreads();
        for (int idx = threadIdx.x; idx < 512 * 16; idx += 256)
            Bsm[idx >> 4][idx & 15] =
                ki[((size_t)(head * S + tc * 512 + (idx >> 4))) * 16 + (idx & 15)];
        __syncthreads();
        #pragma unroll
        for (int kk = 0; kk < 16; kk++) {
            int a0 = Asm[ty * 4 + 0][kk];
            int a1 = Asm[ty * 4 + 1][kk];
            int a2 = Asm[ty * 4 + 2][kk];
            int a3 = Asm[ty * 4 + 3][kk];
            #pragma unroll
            for (int j = 0; j < 16; j++) {
                int bb = Bsm[tx + 32 * j][kk];
                acc[0][tc * 16 + j] = __dp4a(bb, a0, acc[0][tc * 16 + j]);
                acc[1][tc * 16 + j] = __dp4a(bb, a1, acc[1][tc * 16 + j]);
                acc[2][tc * 16 + j] = __dp4a(bb, a2, acc[2][tc * 16 + j]);
                acc[3][tc * 16 + j] = __dp4a(bb, a3, acc[3][tc * 16 + j]);
            }
        }
    }

    const float sq = fmaxf(__fdiv_rn(__uint_as_float(g_stat[0]), 127.0f), 1e-8f);
    const float sk = fmaxf(__fdiv_rn(__uint_as_float(g_stat[1]), 127.0f), 1e-8f);
    const float mult = sq * sk * 0.125f;   // d^-0.5 = 1/8 exact

    #pragma unroll
    for (int ri = 0; ri < 4; ri++) {
        const int row = ty * 4 + ri;
        float m = -3.4e38f;
        #pragma unroll
        for (int jj = 0; jj < 32; jj++) {
            float l = (float)acc[ri][jj] * mult;
            acc[ri][jj] = __float_as_int(l);
            m = fmaxf(m, l);
        }
        #pragma unroll
        for (int o = 16; o; o >>= 1) m = fmaxf(m, __shfl_xor_sync(0xffffffffu, m, o));
        float ssum = 0.0f;
        #pragma unroll
        for (int jj = 0; jj < 32; jj++) {
            float p = expf(__int_as_float(acc[ri][jj]) - m);
            acc[ri][jj] = __float_as_int(p);
            ssum += p;
        }
        #pragma unroll
        for (int o = 16; o; o >>= 1) ssum += __shfl_xor_sync(0xffffffffu, ssum, o);
        const float rden = __frcp_rn(ssum);   // == max prob of this row (exp(0)*rden)
        float* Prow = g_P + ((size_t)head * S + s0 + row) * S;
        #pragma unroll
        for (int jj = 0; jj < 32; jj++) {
            int col = (jj >> 4) * 512 + (jj & 15) * 32 + tx;
            Prow[col] = __int_as_float(acc[ri][jj]) * rden;
        }
        if (tx == 0) atomicMax(&g_stat[3], __float_as_uint(rden));
    }
}

// ------------------------------------------------------------------
// Pass 2: double-quantize P (uint8 grid then sym-127 grid -> k2 in [0,127]),
// dp4a against V (signed), scaled epilogue.  grid (S/64, HEADS), block (32,8)
__global__ __launch_bounds__(256, 2) void k_pass2(float* __restrict__ out) {
    const int head = blockIdx.y;
    const int s0 = blockIdx.x * 64;
    const int tx = threadIdx.x & 31;
    const int ty = threadIdx.x >> 5;

    const float maxp = __uint_as_float(g_stat[3]);
    const float s1 = fmaxf(__fdiv_rn(maxp, 255.0f), 1e-8f);
    const float m2 = 255.0f * s1;                          // max of uint8-quantized probs
    const float s2 = fmaxf(__fdiv_rn(m2, 127.0f), 1e-8f);  // second (sym) scale
    const float sv = fmaxf(__fdiv_rn(__uint_as_float(g_stat[2]), 127.0f), 1e-8f);

    __shared__ int Psm[64][33];
    __shared__ int Vsm[64][33];

    int acc[2][8];
    #pragma unroll
    for (int a = 0; a < 2; a++)
        #pragma unroll
        for (int b = 0; b < 8; b++) acc[a][b] = 0;

    const int* vi = (const int*)g_v8;

    for (int tc = 0; tc < S; tc += 128) {
        if (tc) __syncthreads();
        // load + double-quantize P: 64 rows x 128 cols
        for (int idx = threadIdx.x; idx < 2048; idx += 256) {
            int r = idx >> 5, c = idx & 31;
            float4 x = *(const float4*)(g_P + ((size_t)head * S + s0 + r) * S + tc + c * 4);
            int kq[4];
            float pv[4] = {x.x, x.y, x.z, x.w};
            #pragma unroll
            for (int e = 0; e < 4; e++) {
                float k1 = fminf(fmaxf(rintf(__fdiv_rn(pv[e], s1)), 0.0f), 255.0f);
                float cq = k1 * s1;
                float k2 = fminf(fmaxf(rintf(__fdiv_rn(cq, s2)), 0.0f), 127.0f);
                kq[e] = (int)k2;
            }
            Psm[r][c] = (kq[0] & 0xff) | ((kq[1] & 0xff) << 8) |
                        ((kq[2] & 0xff) << 16) | ((kq[3] & 0xff) << 24);
        }
        // load V: 64 rows x 128 cols (int8)
        for (int idx = threadIdx.x; idx < 2048; idx += 256) {
            int r = idx >> 5, c = idx & 31;
            Vsm[r][c] = vi[((size_t)(head * D + r)) * (S / 4) + tc / 4 + c];
        }
        __syncthreads();
        #pragma unroll
        for (int kk = 0; kk < 32; kk++) {
            int p0 = Psm[tx][kk];
            int p1 = Psm[tx + 32][kk];
            #pragma unroll
            for (int dj = 0; dj < 8; dj++) {
                int vv = Vsm[ty + 8 * dj][kk];
                acc[0][dj] = __dp4a(p0, vv, acc[0][dj]);
                acc[1][dj] = __dp4a(p1, vv, acc[1][dj]);
            }
        }
    }

    const float fs = s2 * sv;
    #pragma unroll
    for (int si = 0; si < 2; si++) {
        #pragma unroll
        for (int dj = 0; dj < 8; dj++) {
            int dd = ty + 8 * dj;
            int ss = s0 + tx + 32 * si;
            out[((size_t)(head * D + dd)) * S + ss] = (float)acc[si][dj] * fs;
        }
    }
}

// ------------------------------------------------------------------
extern "C" void kernel_launch(void* const* d_in, const int* in_sizes, int n_in,
                              void* d_out, int out_size) {
    (void)in_sizes; (void)n_in; (void)out_size;
    const float* q = (const float*)d_in[0];
    const float* k = (const float*)d_in[1];
    const float* v = (const float*)d_in[2];
    float* out = (float*)d_out;

    k_init<<<1, 1>>>();
    k_absmax<<<dim3(148, 3), 256>>>(q, k, v);
    k_quantT<<<dim3(S / 64, HEADS, 2), 256>>>(q, k);
    k_quantV<<<512, 256>>>(v);
    k_pass1<<<dim3(S / 32, HEADS), 256>>>();
    k_pass2<<<dim3(S / 64, HEADS), 256>>>(out);
}